// round 10
// baseline (speedup 1.0000x reference)
#include <cuda_runtime.h>
#include <cuda_fp16.h>
#include <cstdint>

#define NN 100000
#define FD 128
#define NE 1600000
#define NG 64
#define NC 10
#define SCAN_CHUNK 1024
#define SCAN_BLOCKS ((NN + SCAN_CHUNK - 1) / SCAN_CHUNK)   // 98

// ---------------- scratch ----------------
__device__ __half  g_Xh[(size_t)NN * FD];  // activations (half)
__device__ __half  g_Th[(size_t)NN * FD];  // GEMM output (half, gather source)
__device__ __half  g_Wt[3 * FD * FD];      // all W, transposed, half
__device__ float   g_dinv[NN];
__device__ int     g_cntN[NN];
__device__ int     g_rowptr[NN + 1];
__device__ int     g_pos[NN];
__device__ int     g_bsum[128];
__device__ float2  g_sw[NE];               // .x = src (bits), .y = edge weight
__device__ float   g_sums[NG * FD];
__device__ float   g_cnt [NG];
__device__ int     g_is64;

__device__ __forceinline__ int edge_src(const void* ei, int e) {
    return g_is64 ? (int)((const long long*)ei)[e] : ((const int*)ei)[e];
}
__device__ __forceinline__ int edge_dst(const void* ei, int e) {
    return g_is64 ? (int)((const long long*)ei)[(size_t)NE + e]
                  : ((const int*)ei)[(size_t)NE + e];
}
__device__ __forceinline__ int batch_at(const void* b, int v) {
    return g_is64 ? (int)((const long long*)b)[v] : ((const int*)b)[v];
}

// ---------------- fused init: zero counts/pool + convert W + detect dtype ----------------
__global__ void init_all(const int* __restrict__ batch_words,
                         const float* __restrict__ W1,
                         const float* __restrict__ W2,
                         const float* __restrict__ W3) {
    int i = blockIdx.x * blockDim.x + threadIdx.x;
    if (i < NN) g_cntN[i] = 0;
    if (i < NG * FD) g_sums[i] = 0.0f;
    if (i < NG) g_cnt[i] = 0.0f;
    if (i < 3 * FD * FD) {
        int l = i / (FD * FD);
        int j = i % (FD * FD);
        const float* W = (l == 0) ? W1 : (l == 1) ? W2 : W3;
        int k = j >> 7, n = j & 127;
        g_Wt[l * FD * FD + n * FD + k] = __float2half_rn(W[j]);
    }
    // block 0: dtype detection (batch sorted in [0,64))
    if (blockIdx.x == 0) {
        __shared__ int found;
        if (threadIdx.x == 0) found = 0;
        __syncthreads();
        int local = 0;
        for (int t = threadIdx.x; t < NN / 2; t += blockDim.x)
            if (batch_words[2 * t + 1] != 0) local = 1;
        if (local) atomicOr(&found, 1);
        __syncthreads();
        if (threadIdx.x == 0) g_is64 = (found == 0) ? 1 : 0;
    }
}

__global__ void count_edges(const void* __restrict__ ei) {
    int e = blockIdx.x * blockDim.x + threadIdx.x;
    if (e < NE) atomicAdd(&g_cntN[edge_dst(ei, e)], 1);
}

// ---------------- scan (3 phases); scan1 also computes dinv ----------------
__global__ void __launch_bounds__(256) scan1() {
    __shared__ int warp_tot[8];
    int base = blockIdx.x * SCAN_CHUNK + threadIdx.x * 4;
    int lane = threadIdx.x & 31, w = threadIdx.x >> 5;
    int v0 = (base + 0 < NN) ? g_cntN[base + 0] : 0;
    int v1 = (base + 1 < NN) ? g_cntN[base + 1] : 0;
    int v2 = (base + 2 < NN) ? g_cntN[base + 2] : 0;
    int v3 = (base + 3 < NN) ? g_cntN[base + 3] : 0;
    if (base + 0 < NN) g_dinv[base + 0] = rsqrtf((float)(v0 + 1));
    if (base + 1 < NN) g_dinv[base + 1] = rsqrtf((float)(v1 + 1));
    if (base + 2 < NN) g_dinv[base + 2] = rsqrtf((float)(v2 + 1));
    if (base + 3 < NN) g_dinv[base + 3] = rsqrtf((float)(v3 + 1));
    int tot = v0 + v1 + v2 + v3;
    int inc = tot;
#pragma unroll
    for (int o = 1; o < 32; o <<= 1) {
        int t = __shfl_up_sync(~0u, inc, o);
        if (lane >= o) inc += t;
    }
    if (lane == 31) warp_tot[w] = inc;
    __syncthreads();
    if (w == 0 && lane < 8) {
        int t = warp_tot[lane];
#pragma unroll
        for (int o = 1; o < 8; o <<= 1) {
            int u = __shfl_up_sync(0xffu, t, o);
            if (lane >= o) t += u;
        }
        warp_tot[lane] = t;
    }
    __syncthreads();
    int excl = ((w > 0) ? warp_tot[w - 1] : 0) + (inc - tot);
    if (base + 0 < NN) g_rowptr[base + 0] = excl;
    if (base + 1 < NN) g_rowptr[base + 1] = excl + v0;
    if (base + 2 < NN) g_rowptr[base + 2] = excl + v0 + v1;
    if (base + 3 < NN) g_rowptr[base + 3] = excl + v0 + v1 + v2;
    if (threadIdx.x == 255) g_bsum[blockIdx.x] = warp_tot[7];
}
__global__ void __launch_bounds__(128) scan2() {
    __shared__ int wt[4];
    int tid = threadIdx.x, lane = tid & 31, w = tid >> 5;
    int v = (tid < SCAN_BLOCKS) ? g_bsum[tid] : 0;
    int inc = v;
#pragma unroll
    for (int o = 1; o < 32; o <<= 1) {
        int t = __shfl_up_sync(~0u, inc, o);
        if (lane >= o) inc += t;
    }
    if (lane == 31) wt[w] = inc;
    __syncthreads();
    if (w == 0 && lane < 4) {
        int t = wt[lane];
#pragma unroll
        for (int o = 1; o < 4; o <<= 1) {
            int u = __shfl_up_sync(0xfu, t, o);
            if (lane >= o) t += u;
        }
        wt[lane] = t;
    }
    __syncthreads();
    int excl = ((w > 0) ? wt[w - 1] : 0) + (inc - v);
    if (tid < SCAN_BLOCKS) g_bsum[tid] = excl;
    if (tid == 0) g_rowptr[NN] = NE;
}
__global__ void __launch_bounds__(256) scan3() {
    int off = g_bsum[blockIdx.x];
    int base = blockIdx.x * SCAN_CHUNK + threadIdx.x * 4;
#pragma unroll
    for (int j = 0; j < 4; j++) {
        int idx = base + j;
        if (idx < NN) {
            int val = g_rowptr[idx] + off;
            g_rowptr[idx] = val;
            g_pos[idx] = val;
        }
    }
}
__global__ void fill_csr(const void* __restrict__ ei) {
    int e = blockIdx.x * blockDim.x + threadIdx.x;
    if (e >= NE) return;
    int s = edge_src(ei, e);
    int d = edge_dst(ei, e);
    int p = atomicAdd(&g_pos[d], 1);
    g_sw[p] = make_float2(__int_as_float(s), g_dinv[s] * g_dinv[d]);
}

// ---------------- tensor-core GEMM (R6 version — best measured) ----------------
#define AS_STRIDE 136
__global__ void __launch_bounds__(512) gemm_h(const float* __restrict__ Xf, int wsel) {
    __shared__ __align__(16) __half As[128 * AS_STRIDE];
    __shared__ __align__(16) __half Bs[128 * AS_STRIDE];

    const int tid  = threadIdx.x;
    const int warp = tid >> 5;
    const int lane = tid & 31;
    const int wm = warp >> 2;       // 0..3
    const int wn = warp & 3;        // 0..3
    const int row0 = blockIdx.x * 128;
    const int gr = lane >> 2;       // 0..7
    const int ck = (lane & 3) * 2;  // 0,2,4,6
    const __half* Wt = g_Wt + wsel * FD * FD;

    if (Xf != nullptr) {
#pragma unroll
        for (int it = 0; it < 8; it++) {
            int i = tid + it * 512;          // float4 slot, 0..4095
            int r = i >> 5, c4 = i & 31;
            float4 v = make_float4(0.f, 0.f, 0.f, 0.f);
            if (row0 + r < NN)
                v = *(const float4*)(Xf + (size_t)(row0 + r) * FD + c4 * 4);
            __half2 h0 = __floats2half2_rn(v.x, v.y);
            __half2 h1 = __floats2half2_rn(v.z, v.w);
            uint2 u;
            u.x = *(unsigned int*)&h0;
            u.y = *(unsigned int*)&h1;
            *(uint2*)(As + r * AS_STRIDE + c4 * 4) = u;
        }
    } else {
#pragma unroll
        for (int it = 0; it < 4; it++) {
            int i = tid + it * 512;          // uint4 slot, 0..2047
            int r = i >> 4, kq = i & 15;
            uint4 v = make_uint4(0u, 0u, 0u, 0u);
            if (row0 + r < NN)
                v = *(const uint4*)(g_Xh + (size_t)(row0 + r) * FD + kq * 8);
            *(uint4*)(As + r * AS_STRIDE + kq * 8) = v;
        }
    }
#pragma unroll
    for (int it = 0; it < 4; it++) {
        int i = tid + it * 512;
        int nr = i >> 4, kq = i & 15;
        *(uint4*)(Bs + nr * AS_STRIDE + kq * 8) =
            *(const uint4*)(Wt + nr * FD + kq * 8);
    }
    __syncthreads();

    float c[2][4][4];
#pragma unroll
    for (int mi = 0; mi < 2; mi++)
#pragma unroll
        for (int ni = 0; ni < 4; ni++)
#pragma unroll
            for (int q = 0; q < 4; q++) c[mi][ni][q] = 0.0f;

#pragma unroll
    for (int kk = 0; kk < 8; kk++) {
        int kb = kk * 16;
        unsigned int a[2][4];
#pragma unroll
        for (int mi = 0; mi < 2; mi++) {
            const __half* base = As + (wm * 32 + mi * 16 + gr) * AS_STRIDE + kb + ck;
            a[mi][0] = *(const unsigned int*)(base);
            a[mi][1] = *(const unsigned int*)(base + 8 * AS_STRIDE);
            a[mi][2] = *(const unsigned int*)(base + 8);
            a[mi][3] = *(const unsigned int*)(base + 8 * AS_STRIDE + 8);
        }
#pragma unroll
        for (int ni = 0; ni < 4; ni++) {
            const __half* bb = Bs + (wn * 32 + ni * 8 + gr) * AS_STRIDE + kb + ck;
            unsigned int b0 = *(const unsigned int*)(bb);
            unsigned int b1 = *(const unsigned int*)(bb + 8);
#pragma unroll
            for (int mi = 0; mi < 2; mi++) {
                asm volatile(
                    "mma.sync.aligned.m16n8k16.row.col.f32.f16.f16.f32 "
                    "{%0,%1,%2,%3}, {%4,%5,%6,%7}, {%8,%9}, {%0,%1,%2,%3};"
                    : "+f"(c[mi][ni][0]), "+f"(c[mi][ni][1]),
                      "+f"(c[mi][ni][2]), "+f"(c[mi][ni][3])
                    : "r"(a[mi][0]), "r"(a[mi][1]), "r"(a[mi][2]), "r"(a[mi][3]),
                      "r"(b0), "r"(b1));
            }
        }
    }

    const int cc = (lane & 3) * 2;
#pragma unroll
    for (int mi = 0; mi < 2; mi++) {
#pragma unroll
        for (int ni = 0; ni < 4; ni++) {
            int row = row0 + wm * 32 + mi * 16 + gr;
            int col = wn * 32 + ni * 8 + cc;
            if (row < NN) {
                __half2 h0 = __floats2half2_rn(c[mi][ni][0], c[mi][ni][1]);
                *(unsigned int*)(g_Th + (size_t)row * FD + col) = *(unsigned int*)&h0;
            }
            if (row + 8 < NN) {
                __half2 h1 = __floats2half2_rn(c[mi][ni][2], c[mi][ni][3]);
                *(unsigned int*)(g_Th + (size_t)(row + 8) * FD + col) = *(unsigned int*)&h1;
            }
        }
    }
}

// ---------------- fused aggregation: half-warp per node, constant MLP-8 ----------------
__device__ __forceinline__ void acc8(float* a, uint4 u, float w) {
    __half2 h; float2 f;
    h = *(__half2*)&u.x; f = __half22float2(h);
    a[0] = fmaf(f.x, w, a[0]); a[1] = fmaf(f.y, w, a[1]);
    h = *(__half2*)&u.y; f = __half22float2(h);
    a[2] = fmaf(f.x, w, a[2]); a[3] = fmaf(f.y, w, a[3]);
    h = *(__half2*)&u.z; f = __half22float2(h);
    a[4] = fmaf(f.x, w, a[4]); a[5] = fmaf(f.y, w, a[5]);
    h = *(__half2*)&u.w; f = __half22float2(h);
    a[6] = fmaf(f.x, w, a[6]); a[7] = fmaf(f.y, w, a[7]);
}

// mode 0: write relu(acc) half -> g_Xh; mode 1: write acc half (no relu) -> g_Xh
__global__ void __launch_bounds__(256) aggregate(int mode, const float* __restrict__ bias) {
    int gwarp = (blockIdx.x * 256 + threadIdx.x) >> 5;
    int lane = threadIdx.x & 31;
    int node = gwarp * 2 + (lane >> 4);
    int ln = lane & 15;
    if (node >= NN) return;
    int beg = g_rowptr[node], end = g_rowptr[node + 1];
    float di = g_dinv[node];
    float cnorm = di * di;

    float a[8];
    {
        float4 b0 = *(const float4*)(bias + ln * 8);
        float4 b1 = *(const float4*)(bias + ln * 8 + 4);
        a[0] = b0.x; a[1] = b0.y; a[2] = b0.z; a[3] = b0.w;
        a[4] = b1.x; a[5] = b1.y; a[6] = b1.z; a[7] = b1.w;
    }
    {
        uint4 u = *(const uint4*)(g_Th + (size_t)node * FD + ln * 8);
        acc8(a, u, cnorm);
    }

    // constant-MLP batches of 8; out-of-range lanes clamp to last edge with w=0
    for (int i = beg; i < end; i += 8) {
        float2 e[8];
        uint4  u[8];
#pragma unroll
        for (int j = 0; j < 8; j++) {
            int idx = i + j;
            int cidx = (idx < end) ? idx : (end - 1);
            e[j] = g_sw[cidx];
            if (idx >= end) e[j].y = 0.0f;
            u[j] = *(const uint4*)(g_Th + (size_t)__float_as_int(e[j].x) * FD + ln * 8);
        }
#pragma unroll
        for (int j = 0; j < 8; j++) acc8(a, u[j], e[j].y);
    }

    if (mode == 0) {
#pragma unroll
        for (int q = 0; q < 8; q++) a[q] = fmaxf(a[q], 0.f);
    }
    __half2 h0 = __floats2half2_rn(a[0], a[1]);
    __half2 h1 = __floats2half2_rn(a[2], a[3]);
    __half2 h2 = __floats2half2_rn(a[4], a[5]);
    __half2 h3 = __floats2half2_rn(a[6], a[7]);
    uint4 u;
    u.x = *(unsigned int*)&h0;
    u.y = *(unsigned int*)&h1;
    u.z = *(unsigned int*)&h2;
    u.w = *(unsigned int*)&h3;
    *(uint4*)(g_Xh + (size_t)node * FD + ln * 8) = u;
}

// ---------------- pooling: 64 nodes per block ----------------
#define POOL_NODES 64
__global__ void __launch_bounds__(128) pool_accum(const void* __restrict__ batch, int n) {
    __shared__ int sb[POOL_NODES];
    int f  = threadIdx.x;
    int v0 = blockIdx.x * POOL_NODES;
    for (int i = f; i < POOL_NODES; i += 128) {
        int v = v0 + i;
        sb[i] = (v < n) ? batch_at(batch, v) : -1;
    }
    __syncthreads();
    float acc = 0.f, ccnt = 0.f;
    int curg = -1;
    for (int i = 0; i < POOL_NODES; i++) {
        int g = sb[i];
        if (g < 0) break;
        if (g != curg) {
            if (curg >= 0) {
                atomicAdd(&g_sums[curg * FD + f], acc);
                if (f == 0) atomicAdd(&g_cnt[curg], ccnt);
            }
            acc = 0.f; ccnt = 0.f; curg = g;
        }
        acc  += __half2float(g_Xh[(size_t)(v0 + i) * FD + f]);
        ccnt += 1.f;
    }
    if (curg >= 0) {
        atomicAdd(&g_sums[curg * FD + f], acc);
        if (f == 0) atomicAdd(&g_cnt[curg], ccnt);
    }
}

// ---------------- finalize ----------------
__global__ void __launch_bounds__(128) finalize(
    const float* __restrict__ Wlin, const float* __restrict__ blin,
    float* __restrict__ out, int out_size)
{
    int g = blockIdx.x;
    int f = threadIdx.x;
    __shared__ float se[FD];
    float e = g_sums[g * FD + f] / fmaxf(g_cnt[g], 1.0f);
    se[f] = e;
    if (out_size >= NG * NC + NG * FD)
        out[NG * NC + g * FD + f] = e;
    __syncthreads();
    if (f < NC) {
        float s = blin[f];
#pragma unroll
        for (int k = 0; k < FD; k++)
            s = fmaf(se[k], Wlin[k * NC + f], s);
        out[g * NC + f] = s;
    }
}

// ---------------- launch ----------------
extern "C" void kernel_launch(void* const* d_in, const int* in_sizes, int n_in,
                              void* d_out, int out_size) {
    const float* x    = (const float*)d_in[0];
    const void*  ei   = d_in[1];
    const void*  batch= d_in[2];
    const float* W1   = (const float*)d_in[3];
    const float* b1   = (const float*)d_in[4];
    const float* W2   = (const float*)d_in[5];
    const float* b2   = (const float*)d_in[6];
    const float* W3   = (const float*)d_in[7];
    const float* b3   = (const float*)d_in[8];
    const float* Wlin = (const float*)d_in[9];
    const float* blin = (const float*)d_in[10];
    float* out = (float*)d_out;
    const int n = NN;

    const int gemm_grid = (NN + 127) / 128;
    const int agg_grid  = (NN * 16 + 255) / 256;

    init_all   <<<(NN + 255) / 256, 256>>>((const int*)batch, W1, W2, W3); // 0
    count_edges<<<(NE + 255) / 256, 256>>>(ei);                            // 1
    gemm_h     <<<gemm_grid, 512>>>(x, 0);                                 // 2
    scan1      <<<SCAN_BLOCKS, 256>>>();                                   // 3
    scan2      <<<1, 128>>>();                                             // 4
    scan3      <<<SCAN_BLOCKS, 256>>>();                                   // 5
    fill_csr   <<<(NE + 255) / 256, 256>>>(ei);                            // 6

    aggregate  <<<agg_grid, 256>>>(0, b1);     // -> relu half Xh
    gemm_h     <<<gemm_grid, 512>>>(nullptr, 1);
    aggregate  <<<agg_grid, 256>>>(0, b2);     // -> relu half Xh
    gemm_h     <<<gemm_grid, 512>>>(nullptr, 2);
    aggregate  <<<agg_grid, 256>>>(1, b3);     // -> half Xh (no relu)

    pool_accum<<<(NN + POOL_NODES - 1) / POOL_NODES, 128>>>(batch, n);
    finalize  <<<NG, 128>>>(Wlin, blin, out, out_size);
}

// round 11
// speedup vs baseline: 1.0856x; 1.0856x over previous
#include <cuda_runtime.h>
#include <cuda_fp16.h>
#include <cstdint>

#define NN 100000
#define FD 128
#define NE 1600000
#define NG 64
#define NC 10
#define SCAN_CHUNK 1024
#define SCAN_BLOCKS ((NN + SCAN_CHUNK - 1) / SCAN_CHUNK)   // 98

// ---------------- scratch ----------------
__device__ __half  g_Xh[(size_t)NN * FD];  // activations (half)
__device__ __half  g_Th[(size_t)NN * FD];  // GEMM output (half, gather source)
__device__ __half  g_Wt[3 * FD * FD];      // all W, transposed, half
__device__ float   g_dinv[NN];
__device__ int     g_cntN[NN];
__device__ int     g_rowptr[NN + 1];
__device__ int     g_pos[NN];
__device__ int     g_bsum[128];
__device__ float2  g_sw[NE];               // .x = src (bits), .y = edge weight
__device__ float   g_sums[NG * FD];
__device__ float   g_cnt [NG];
__device__ int     g_is64;

__device__ __forceinline__ int edge_src(const void* ei, int e) {
    return g_is64 ? (int)((const long long*)ei)[e] : ((const int*)ei)[e];
}
__device__ __forceinline__ int edge_dst(const void* ei, int e) {
    return g_is64 ? (int)((const long long*)ei)[(size_t)NE + e]
                  : ((const int*)ei)[(size_t)NE + e];
}
__device__ __forceinline__ int batch_at(const void* b, int v) {
    return g_is64 ? (int)((const long long*)b)[v] : ((const int*)b)[v];
}

// ---------------- fused init: zero counts/pool + convert W + detect dtype ----------------
__global__ void init_all(const int* __restrict__ batch_words,
                         const float* __restrict__ W1,
                         const float* __restrict__ W2,
                         const float* __restrict__ W3) {
    int i = blockIdx.x * blockDim.x + threadIdx.x;
    if (i < NN) g_cntN[i] = 0;
    if (i < NG * FD) g_sums[i] = 0.0f;
    if (i < NG) g_cnt[i] = 0.0f;
    if (i < 3 * FD * FD) {
        int l = i / (FD * FD);
        int j = i % (FD * FD);
        const float* W = (l == 0) ? W1 : (l == 1) ? W2 : W3;
        int k = j >> 7, n = j & 127;
        g_Wt[l * FD * FD + n * FD + k] = __float2half_rn(W[j]);
    }
    // block 0: dtype detection (batch sorted in [0,64))
    if (blockIdx.x == 0) {
        __shared__ int found;
        if (threadIdx.x == 0) found = 0;
        __syncthreads();
        int local = 0;
        for (int t = threadIdx.x; t < NN / 2; t += blockDim.x)
            if (batch_words[2 * t + 1] != 0) local = 1;
        if (local) atomicOr(&found, 1);
        __syncthreads();
        if (threadIdx.x == 0) g_is64 = (found == 0) ? 1 : 0;
    }
}

__global__ void count_edges(const void* __restrict__ ei) {
    int e = blockIdx.x * blockDim.x + threadIdx.x;
    if (e < NE) atomicAdd(&g_cntN[edge_dst(ei, e)], 1);
}

// ---------------- scan (3 phases); scan1 also computes dinv ----------------
__global__ void __launch_bounds__(256) scan1() {
    __shared__ int warp_tot[8];
    int base = blockIdx.x * SCAN_CHUNK + threadIdx.x * 4;
    int lane = threadIdx.x & 31, w = threadIdx.x >> 5;
    int v0 = (base + 0 < NN) ? g_cntN[base + 0] : 0;
    int v1 = (base + 1 < NN) ? g_cntN[base + 1] : 0;
    int v2 = (base + 2 < NN) ? g_cntN[base + 2] : 0;
    int v3 = (base + 3 < NN) ? g_cntN[base + 3] : 0;
    if (base + 0 < NN) g_dinv[base + 0] = rsqrtf((float)(v0 + 1));
    if (base + 1 < NN) g_dinv[base + 1] = rsqrtf((float)(v1 + 1));
    if (base + 2 < NN) g_dinv[base + 2] = rsqrtf((float)(v2 + 1));
    if (base + 3 < NN) g_dinv[base + 3] = rsqrtf((float)(v3 + 1));
    int tot = v0 + v1 + v2 + v3;
    int inc = tot;
#pragma unroll
    for (int o = 1; o < 32; o <<= 1) {
        int t = __shfl_up_sync(~0u, inc, o);
        if (lane >= o) inc += t;
    }
    if (lane == 31) warp_tot[w] = inc;
    __syncthreads();
    if (w == 0 && lane < 8) {
        int t = warp_tot[lane];
#pragma unroll
        for (int o = 1; o < 8; o <<= 1) {
            int u = __shfl_up_sync(0xffu, t, o);
            if (lane >= o) t += u;
        }
        warp_tot[lane] = t;
    }
    __syncthreads();
    int excl = ((w > 0) ? warp_tot[w - 1] : 0) + (inc - tot);
    if (base + 0 < NN) g_rowptr[base + 0] = excl;
    if (base + 1 < NN) g_rowptr[base + 1] = excl + v0;
    if (base + 2 < NN) g_rowptr[base + 2] = excl + v0 + v1;
    if (base + 3 < NN) g_rowptr[base + 3] = excl + v0 + v1 + v2;
    if (threadIdx.x == 255) g_bsum[blockIdx.x] = warp_tot[7];
}
__global__ void __launch_bounds__(128) scan2() {
    __shared__ int wt[4];
    int tid = threadIdx.x, lane = tid & 31, w = tid >> 5;
    int v = (tid < SCAN_BLOCKS) ? g_bsum[tid] : 0;
    int inc = v;
#pragma unroll
    for (int o = 1; o < 32; o <<= 1) {
        int t = __shfl_up_sync(~0u, inc, o);
        if (lane >= o) inc += t;
    }
    if (lane == 31) wt[w] = inc;
    __syncthreads();
    if (w == 0 && lane < 4) {
        int t = wt[lane];
#pragma unroll
        for (int o = 1; o < 4; o <<= 1) {
            int u = __shfl_up_sync(0xfu, t, o);
            if (lane >= o) t += u;
        }
        wt[lane] = t;
    }
    __syncthreads();
    int excl = ((w > 0) ? wt[w - 1] : 0) + (inc - v);
    if (tid < SCAN_BLOCKS) g_bsum[tid] = excl;
    if (tid == 0) g_rowptr[NN] = NE;
}
__global__ void __launch_bounds__(256) scan3() {
    int off = g_bsum[blockIdx.x];
    int base = blockIdx.x * SCAN_CHUNK + threadIdx.x * 4;
#pragma unroll
    for (int j = 0; j < 4; j++) {
        int idx = base + j;
        if (idx < NN) {
            int val = g_rowptr[idx] + off;
            g_rowptr[idx] = val;
            g_pos[idx] = val;
        }
    }
}
__global__ void fill_csr(const void* __restrict__ ei) {
    int e = blockIdx.x * blockDim.x + threadIdx.x;
    if (e >= NE) return;
    int s = edge_src(ei, e);
    int d = edge_dst(ei, e);
    int p = atomicAdd(&g_pos[d], 1);
    g_sw[p] = make_float2(__int_as_float(s), g_dinv[s] * g_dinv[d]);
}

// ---------------- tensor-core GEMM (R6 version — best measured) ----------------
#define AS_STRIDE 136
__global__ void __launch_bounds__(512) gemm_h(const float* __restrict__ Xf, int wsel) {
    __shared__ __align__(16) __half As[128 * AS_STRIDE];
    __shared__ __align__(16) __half Bs[128 * AS_STRIDE];

    const int tid  = threadIdx.x;
    const int warp = tid >> 5;
    const int lane = tid & 31;
    const int wm = warp >> 2;       // 0..3
    const int wn = warp & 3;        // 0..3
    const int row0 = blockIdx.x * 128;
    const int gr = lane >> 2;       // 0..7
    const int ck = (lane & 3) * 2;  // 0,2,4,6
    const __half* Wt = g_Wt + wsel * FD * FD;

    if (Xf != nullptr) {
#pragma unroll
        for (int it = 0; it < 8; it++) {
            int i = tid + it * 512;          // float4 slot, 0..4095
            int r = i >> 5, c4 = i & 31;
            float4 v = make_float4(0.f, 0.f, 0.f, 0.f);
            if (row0 + r < NN)
                v = *(const float4*)(Xf + (size_t)(row0 + r) * FD + c4 * 4);
            __half2 h0 = __floats2half2_rn(v.x, v.y);
            __half2 h1 = __floats2half2_rn(v.z, v.w);
            uint2 u;
            u.x = *(unsigned int*)&h0;
            u.y = *(unsigned int*)&h1;
            *(uint2*)(As + r * AS_STRIDE + c4 * 4) = u;
        }
    } else {
#pragma unroll
        for (int it = 0; it < 4; it++) {
            int i = tid + it * 512;          // uint4 slot, 0..2047
            int r = i >> 4, kq = i & 15;
            uint4 v = make_uint4(0u, 0u, 0u, 0u);
            if (row0 + r < NN)
                v = *(const uint4*)(g_Xh + (size_t)(row0 + r) * FD + kq * 8);
            *(uint4*)(As + r * AS_STRIDE + kq * 8) = v;
        }
    }
#pragma unroll
    for (int it = 0; it < 4; it++) {
        int i = tid + it * 512;
        int nr = i >> 4, kq = i & 15;
        *(uint4*)(Bs + nr * AS_STRIDE + kq * 8) =
            *(const uint4*)(Wt + nr * FD + kq * 8);
    }
    __syncthreads();

    float c[2][4][4];
#pragma unroll
    for (int mi = 0; mi < 2; mi++)
#pragma unroll
        for (int ni = 0; ni < 4; ni++)
#pragma unroll
            for (int q = 0; q < 4; q++) c[mi][ni][q] = 0.0f;

#pragma unroll
    for (int kk = 0; kk < 8; kk++) {
        int kb = kk * 16;
        unsigned int a[2][4];
#pragma unroll
        for (int mi = 0; mi < 2; mi++) {
            const __half* base = As + (wm * 32 + mi * 16 + gr) * AS_STRIDE + kb + ck;
            a[mi][0] = *(const unsigned int*)(base);
            a[mi][1] = *(const unsigned int*)(base + 8 * AS_STRIDE);
            a[mi][2] = *(const unsigned int*)(base + 8);
            a[mi][3] = *(const unsigned int*)(base + 8 * AS_STRIDE + 8);
        }
#pragma unroll
        for (int ni = 0; ni < 4; ni++) {
            const __half* bb = Bs + (wn * 32 + ni * 8 + gr) * AS_STRIDE + kb + ck;
            unsigned int b0 = *(const unsigned int*)(bb);
            unsigned int b1 = *(const unsigned int*)(bb + 8);
#pragma unroll
            for (int mi = 0; mi < 2; mi++) {
                asm volatile(
                    "mma.sync.aligned.m16n8k16.row.col.f32.f16.f16.f32 "
                    "{%0,%1,%2,%3}, {%4,%5,%6,%7}, {%8,%9}, {%0,%1,%2,%3};"
                    : "+f"(c[mi][ni][0]), "+f"(c[mi][ni][1]),
                      "+f"(c[mi][ni][2]), "+f"(c[mi][ni][3])
                    : "r"(a[mi][0]), "r"(a[mi][1]), "r"(a[mi][2]), "r"(a[mi][3]),
                      "r"(b0), "r"(b1));
            }
        }
    }

    const int cc = (lane & 3) * 2;
#pragma unroll
    for (int mi = 0; mi < 2; mi++) {
#pragma unroll
        for (int ni = 0; ni < 4; ni++) {
            int row = row0 + wm * 32 + mi * 16 + gr;
            int col = wn * 32 + ni * 8 + cc;
            if (row < NN) {
                __half2 h0 = __floats2half2_rn(c[mi][ni][0], c[mi][ni][1]);
                *(unsigned int*)(g_Th + (size_t)row * FD + col) = *(unsigned int*)&h0;
            }
            if (row + 8 < NN) {
                __half2 h1 = __floats2half2_rn(c[mi][ni][2], c[mi][ni][3]);
                *(unsigned int*)(g_Th + (size_t)(row + 8) * FD + col) = *(unsigned int*)&h1;
            }
        }
    }
}

// ---------------- fused aggregation: half-warp per node, unroll-8 (R9 version) ----------------
__device__ __forceinline__ void acc8(float* a, uint4 u, float w) {
    __half2 h; float2 f;
    h = *(__half2*)&u.x; f = __half22float2(h);
    a[0] = fmaf(f.x, w, a[0]); a[1] = fmaf(f.y, w, a[1]);
    h = *(__half2*)&u.y; f = __half22float2(h);
    a[2] = fmaf(f.x, w, a[2]); a[3] = fmaf(f.y, w, a[3]);
    h = *(__half2*)&u.z; f = __half22float2(h);
    a[4] = fmaf(f.x, w, a[4]); a[5] = fmaf(f.y, w, a[5]);
    h = *(__half2*)&u.w; f = __half22float2(h);
    a[6] = fmaf(f.x, w, a[6]); a[7] = fmaf(f.y, w, a[7]);
}

// mode 0: write relu(acc) half -> g_Xh; mode 1: write acc half (no relu) -> g_Xh
__global__ void __launch_bounds__(256) aggregate(int mode, const float* __restrict__ bias) {
    int gwarp = (blockIdx.x * 256 + threadIdx.x) >> 5;
    int lane = threadIdx.x & 31;
    int node = gwarp * 2 + (lane >> 4);
    int ln = lane & 15;
    if (node >= NN) return;
    int beg = g_rowptr[node], end = g_rowptr[node + 1];
    float di = g_dinv[node];
    float cnorm = di * di;

    float a[8];
    {
        float4 b0 = *(const float4*)(bias + ln * 8);
        float4 b1 = *(const float4*)(bias + ln * 8 + 4);
        a[0] = b0.x; a[1] = b0.y; a[2] = b0.z; a[3] = b0.w;
        a[4] = b1.x; a[5] = b1.y; a[6] = b1.z; a[7] = b1.w;
    }
    {
        uint4 u = *(const uint4*)(g_Th + (size_t)node * FD + ln * 8);
        acc8(a, u, cnorm);
    }

    int i = beg;
    for (; i + 8 <= end; i += 8) {
        float2 e0 = g_sw[i + 0];
        float2 e1 = g_sw[i + 1];
        float2 e2 = g_sw[i + 2];
        float2 e3 = g_sw[i + 3];
        float2 e4 = g_sw[i + 4];
        float2 e5 = g_sw[i + 5];
        float2 e6 = g_sw[i + 6];
        float2 e7 = g_sw[i + 7];
        uint4 u0 = *(const uint4*)(g_Th + (size_t)__float_as_int(e0.x) * FD + ln * 8);
        uint4 u1 = *(const uint4*)(g_Th + (size_t)__float_as_int(e1.x) * FD + ln * 8);
        uint4 u2 = *(const uint4*)(g_Th + (size_t)__float_as_int(e2.x) * FD + ln * 8);
        uint4 u3 = *(const uint4*)(g_Th + (size_t)__float_as_int(e3.x) * FD + ln * 8);
        uint4 u4 = *(const uint4*)(g_Th + (size_t)__float_as_int(e4.x) * FD + ln * 8);
        uint4 u5 = *(const uint4*)(g_Th + (size_t)__float_as_int(e5.x) * FD + ln * 8);
        uint4 u6 = *(const uint4*)(g_Th + (size_t)__float_as_int(e6.x) * FD + ln * 8);
        uint4 u7 = *(const uint4*)(g_Th + (size_t)__float_as_int(e7.x) * FD + ln * 8);
        acc8(a, u0, e0.y);
        acc8(a, u1, e1.y);
        acc8(a, u2, e2.y);
        acc8(a, u3, e3.y);
        acc8(a, u4, e4.y);
        acc8(a, u5, e5.y);
        acc8(a, u6, e6.y);
        acc8(a, u7, e7.y);
    }
    if (i + 4 <= end) {
        float2 e0 = g_sw[i + 0];
        float2 e1 = g_sw[i + 1];
        float2 e2 = g_sw[i + 2];
        float2 e3 = g_sw[i + 3];
        uint4 u0 = *(const uint4*)(g_Th + (size_t)__float_as_int(e0.x) * FD + ln * 8);
        uint4 u1 = *(const uint4*)(g_Th + (size_t)__float_as_int(e1.x) * FD + ln * 8);
        uint4 u2 = *(const uint4*)(g_Th + (size_t)__float_as_int(e2.x) * FD + ln * 8);
        uint4 u3 = *(const uint4*)(g_Th + (size_t)__float_as_int(e3.x) * FD + ln * 8);
        acc8(a, u0, e0.y);
        acc8(a, u1, e1.y);
        acc8(a, u2, e2.y);
        acc8(a, u3, e3.y);
        i += 4;
    }
    for (; i < end; i++) {
        float2 e0 = g_sw[i];
        uint4 u0 = *(const uint4*)(g_Th + (size_t)__float_as_int(e0.x) * FD + ln * 8);
        acc8(a, u0, e0.y);
    }

    if (mode == 0) {
#pragma unroll
        for (int q = 0; q < 8; q++) a[q] = fmaxf(a[q], 0.f);
    }
    __half2 h0 = __floats2half2_rn(a[0], a[1]);
    __half2 h1 = __floats2half2_rn(a[2], a[3]);
    __half2 h2 = __floats2half2_rn(a[4], a[5]);
    __half2 h3 = __floats2half2_rn(a[6], a[7]);
    uint4 u;
    u.x = *(unsigned int*)&h0;
    u.y = *(unsigned int*)&h1;
    u.z = *(unsigned int*)&h2;
    u.w = *(unsigned int*)&h3;
    *(uint4*)(g_Xh + (size_t)node * FD + ln * 8) = u;
}

// ---------------- pooling: 64 nodes per block ----------------
#define POOL_NODES 64
__global__ void __launch_bounds__(128) pool_accum(const void* __restrict__ batch, int n) {
    __shared__ int sb[POOL_NODES];
    int f  = threadIdx.x;
    int v0 = blockIdx.x * POOL_NODES;
    for (int i = f; i < POOL_NODES; i += 128) {
        int v = v0 + i;
        sb[i] = (v < n) ? batch_at(batch, v) : -1;
    }
    __syncthreads();
    float acc = 0.f, ccnt = 0.f;
    int curg = -1;
    for (int i = 0; i < POOL_NODES; i++) {
        int g = sb[i];
        if (g < 0) break;
        if (g != curg) {
            if (curg >= 0) {
                atomicAdd(&g_sums[curg * FD + f], acc);
                if (f == 0) atomicAdd(&g_cnt[curg], ccnt);
            }
            acc = 0.f; ccnt = 0.f; curg = g;
        }
        acc  += __half2float(g_Xh[(size_t)(v0 + i) * FD + f]);
        ccnt += 1.f;
    }
    if (curg >= 0) {
        atomicAdd(&g_sums[curg * FD + f], acc);
        if (f == 0) atomicAdd(&g_cnt[curg], ccnt);
    }
}

// ---------------- finalize ----------------
__global__ void __launch_bounds__(128) finalize(
    const float* __restrict__ Wlin, const float* __restrict__ blin,
    float* __restrict__ out, int out_size)
{
    int g = blockIdx.x;
    int f = threadIdx.x;
    __shared__ float se[FD];
    float e = g_sums[g * FD + f] / fmaxf(g_cnt[g], 1.0f);
    se[f] = e;
    if (out_size >= NG * NC + NG * FD)
        out[NG * NC + g * FD + f] = e;
    __syncthreads();
    if (f < NC) {
        float s = blin[f];
#pragma unroll
        for (int k = 0; k < FD; k++)
            s = fmaf(se[k], Wlin[k * NC + f], s);
        out[g * NC + f] = s;
    }
}

// ---------------- launch ----------------
extern "C" void kernel_launch(void* const* d_in, const int* in_sizes, int n_in,
                              void* d_out, int out_size) {
    const float* x    = (const float*)d_in[0];
    const void*  ei   = d_in[1];
    const void*  batch= d_in[2];
    const float* W1   = (const float*)d_in[3];
    const float* b1   = (const float*)d_in[4];
    const float* W2   = (const float*)d_in[5];
    const float* b2   = (const float*)d_in[6];
    const float* W3   = (const float*)d_in[7];
    const float* b3   = (const float*)d_in[8];
    const float* Wlin = (const float*)d_in[9];
    const float* blin = (const float*)d_in[10];
    float* out = (float*)d_out;
    const int n = NN;

    const int gemm_grid = (NN + 127) / 128;
    const int agg_grid  = (NN * 16 + 255) / 256;

    init_all   <<<(NN + 255) / 256, 256>>>((const int*)batch, W1, W2, W3); // 0
    count_edges<<<(NE + 255) / 256, 256>>>(ei);                            // 1
    gemm_h     <<<gemm_grid, 512>>>(x, 0);                                 // 2
    scan1      <<<SCAN_BLOCKS, 256>>>();                                   // 3
    scan2      <<<1, 128>>>();                                             // 4
    scan3      <<<SCAN_BLOCKS, 256>>>();                                   // 5
    fill_csr   <<<(NE + 255) / 256, 256>>>(ei);                            // 6

    aggregate  <<<agg_grid, 256>>>(0, b1);     // -> relu half Xh
    gemm_h     <<<gemm_grid, 512>>>(nullptr, 1);
    aggregate  <<<agg_grid, 256>>>(0, b2);     // -> relu half Xh
    gemm_h     <<<gemm_grid, 512>>>(nullptr, 2);
    aggregate  <<<agg_grid, 256>>>(1, b3);     // -> half Xh (no relu)

    pool_accum<<<(NN + POOL_NODES - 1) / POOL_NODES, 128>>>(batch, n);
    finalize  <<<NG, 128>>>(Wlin, blin, out, out_size);
}

// round 12
// speedup vs baseline: 1.1291x; 1.0401x over previous
#include <cuda_runtime.h>
#include <cuda_fp16.h>
#include <cstdint>

#define NN 100000
#define FD 128
#define NE 1600000
#define NG 64
#define NC 10
#define SCAN_CHUNK 1024
#define SCAN_BLOCKS ((NN + SCAN_CHUNK - 1) / SCAN_CHUNK)   // 98

// ---------------- scratch ----------------
__device__ __half  g_Xh[(size_t)NN * FD];  // activations (half)
__device__ __half  g_Th[(size_t)NN * FD];  // GEMM output (half, gather source)
__device__ __half  g_Wt[3 * FD * FD];      // all W, transposed, half
__device__ float   g_dinv[NN];
__device__ int     g_cntN[NN];
__device__ int     g_rowptr[NN + 1];
__device__ int     g_pos[NN];
__device__ int     g_bsum[128];
__device__ float2  g_sw[NE];               // .x = src (bits), .y = edge weight
__device__ float   g_sums[NG * FD];
__device__ float   g_cnt [NG];
__device__ int     g_is64;

__device__ __forceinline__ int edge_src(const void* ei, int e) {
    return g_is64 ? (int)((const long long*)ei)[e] : ((const int*)ei)[e];
}
__device__ __forceinline__ int edge_dst(const void* ei, int e) {
    return g_is64 ? (int)((const long long*)ei)[(size_t)NE + e]
                  : ((const int*)ei)[(size_t)NE + e];
}
__device__ __forceinline__ int batch_at(const void* b, int v) {
    return g_is64 ? (int)((const long long*)b)[v] : ((const int*)b)[v];
}

// ---------------- fused init: zero counts/pool + convert W + detect dtype ----------------
__global__ void init_all(const int* __restrict__ batch_words,
                         const float* __restrict__ W1,
                         const float* __restrict__ W2,
                         const float* __restrict__ W3) {
    int i = blockIdx.x * blockDim.x + threadIdx.x;
    if (i < NN) g_cntN[i] = 0;
    if (i < NG * FD) g_sums[i] = 0.0f;
    if (i < NG) g_cnt[i] = 0.0f;
    if (i < 3 * FD * FD) {
        int l = i / (FD * FD);
        int j = i % (FD * FD);
        const float* W = (l == 0) ? W1 : (l == 1) ? W2 : W3;
        int k = j >> 7, n = j & 127;
        g_Wt[l * FD * FD + n * FD + k] = __float2half_rn(W[j]);
    }
    if (blockIdx.x == 0) {
        __shared__ int found;
        if (threadIdx.x == 0) found = 0;
        __syncthreads();
        int local = 0;
        for (int t = threadIdx.x; t < NN / 2; t += blockDim.x)
            if (batch_words[2 * t + 1] != 0) local = 1;
        if (local) atomicOr(&found, 1);
        __syncthreads();
        if (threadIdx.x == 0) g_is64 = (found == 0) ? 1 : 0;
    }
}

__global__ void count_edges(const void* __restrict__ ei) {
    int e = blockIdx.x * blockDim.x + threadIdx.x;
    if (e < NE) atomicAdd(&g_cntN[edge_dst(ei, e)], 1);
}

// ---------------- scan (3 phases); scan1 also computes dinv ----------------
__global__ void __launch_bounds__(256) scan1() {
    __shared__ int warp_tot[8];
    int base = blockIdx.x * SCAN_CHUNK + threadIdx.x * 4;
    int lane = threadIdx.x & 31, w = threadIdx.x >> 5;
    int v0 = (base + 0 < NN) ? g_cntN[base + 0] : 0;
    int v1 = (base + 1 < NN) ? g_cntN[base + 1] : 0;
    int v2 = (base + 2 < NN) ? g_cntN[base + 2] : 0;
    int v3 = (base + 3 < NN) ? g_cntN[base + 3] : 0;
    if (base + 0 < NN) g_dinv[base + 0] = rsqrtf((float)(v0 + 1));
    if (base + 1 < NN) g_dinv[base + 1] = rsqrtf((float)(v1 + 1));
    if (base + 2 < NN) g_dinv[base + 2] = rsqrtf((float)(v2 + 1));
    if (base + 3 < NN) g_dinv[base + 3] = rsqrtf((float)(v3 + 1));
    int tot = v0 + v1 + v2 + v3;
    int inc = tot;
#pragma unroll
    for (int o = 1; o < 32; o <<= 1) {
        int t = __shfl_up_sync(~0u, inc, o);
        if (lane >= o) inc += t;
    }
    if (lane == 31) warp_tot[w] = inc;
    __syncthreads();
    if (w == 0 && lane < 8) {
        int t = warp_tot[lane];
#pragma unroll
        for (int o = 1; o < 8; o <<= 1) {
            int u = __shfl_up_sync(0xffu, t, o);
            if (lane >= o) t += u;
        }
        warp_tot[lane] = t;
    }
    __syncthreads();
    int excl = ((w > 0) ? warp_tot[w - 1] : 0) + (inc - tot);
    if (base + 0 < NN) g_rowptr[base + 0] = excl;
    if (base + 1 < NN) g_rowptr[base + 1] = excl + v0;
    if (base + 2 < NN) g_rowptr[base + 2] = excl + v0 + v1;
    if (base + 3 < NN) g_rowptr[base + 3] = excl + v0 + v1 + v2;
    if (threadIdx.x == 255) g_bsum[blockIdx.x] = warp_tot[7];
}
__global__ void __launch_bounds__(128) scan2() {
    __shared__ int wt[4];
    int tid = threadIdx.x, lane = tid & 31, w = tid >> 5;
    int v = (tid < SCAN_BLOCKS) ? g_bsum[tid] : 0;
    int inc = v;
#pragma unroll
    for (int o = 1; o < 32; o <<= 1) {
        int t = __shfl_up_sync(~0u, inc, o);
        if (lane >= o) inc += t;
    }
    if (lane == 31) wt[w] = inc;
    __syncthreads();
    if (w == 0 && lane < 4) {
        int t = wt[lane];
#pragma unroll
        for (int o = 1; o < 4; o <<= 1) {
            int u = __shfl_up_sync(0xfu, t, o);
            if (lane >= o) t += u;
        }
        wt[lane] = t;
    }
    __syncthreads();
    int excl = ((w > 0) ? wt[w - 1] : 0) + (inc - v);
    if (tid < SCAN_BLOCKS) g_bsum[tid] = excl;
    if (tid == 0) g_rowptr[NN] = NE;
}
__global__ void __launch_bounds__(256) scan3() {
    int off = g_bsum[blockIdx.x];
    int base = blockIdx.x * SCAN_CHUNK + threadIdx.x * 4;
#pragma unroll
    for (int j = 0; j < 4; j++) {
        int idx = base + j;
        if (idx < NN) {
            int val = g_rowptr[idx] + off;
            g_rowptr[idx] = val;
            g_pos[idx] = val;
        }
    }
}
__global__ void fill_csr(const void* __restrict__ ei) {
    int e = blockIdx.x * blockDim.x + threadIdx.x;
    if (e >= NE) return;
    int s = edge_src(ei, e);
    int d = edge_dst(ei, e);
    int p = atomicAdd(&g_pos[d], 1);
    g_sw[p] = make_float2(__int_as_float(s), g_dinv[s] * g_dinv[d]);
}

// ---------------- tensor-core GEMM: R6 mainloop + smem-staged coalesced epilogue ----------------
#define AS_STRIDE 136
__global__ void __launch_bounds__(512) gemm_h(const float* __restrict__ Xf, int wsel) {
    __shared__ __align__(16) __half As[128 * AS_STRIDE];
    __shared__ __align__(16) __half Bs[128 * AS_STRIDE];

    const int tid  = threadIdx.x;
    const int warp = tid >> 5;
    const int lane = tid & 31;
    const int wm = warp >> 2;       // 0..3
    const int wn = warp & 3;        // 0..3
    const int row0 = blockIdx.x * 128;
    const int gr = lane >> 2;       // 0..7
    const int ck = (lane & 3) * 2;  // 0,2,4,6
    const __half* Wt = g_Wt + wsel * FD * FD;

    if (Xf != nullptr) {
#pragma unroll
        for (int it = 0; it < 8; it++) {
            int i = tid + it * 512;          // float4 slot, 0..4095
            int r = i >> 5, c4 = i & 31;
            float4 v = make_float4(0.f, 0.f, 0.f, 0.f);
            if (row0 + r < NN)
                v = *(const float4*)(Xf + (size_t)(row0 + r) * FD + c4 * 4);
            __half2 h0 = __floats2half2_rn(v.x, v.y);
            __half2 h1 = __floats2half2_rn(v.z, v.w);
            uint2 u;
            u.x = *(unsigned int*)&h0;
            u.y = *(unsigned int*)&h1;
            *(uint2*)(As + r * AS_STRIDE + c4 * 4) = u;
        }
    } else {
#pragma unroll
        for (int it = 0; it < 4; it++) {
            int i = tid + it * 512;          // uint4 slot, 0..2047
            int r = i >> 4, kq = i & 15;
            uint4 v = make_uint4(0u, 0u, 0u, 0u);
            if (row0 + r < NN)
                v = *(const uint4*)(g_Xh + (size_t)(row0 + r) * FD + kq * 8);
            *(uint4*)(As + r * AS_STRIDE + kq * 8) = v;
        }
    }
#pragma unroll
    for (int it = 0; it < 4; it++) {
        int i = tid + it * 512;
        int nr = i >> 4, kq = i & 15;
        *(uint4*)(Bs + nr * AS_STRIDE + kq * 8) =
            *(const uint4*)(Wt + nr * FD + kq * 8);
    }
    __syncthreads();

    float c[2][4][4];
#pragma unroll
    for (int mi = 0; mi < 2; mi++)
#pragma unroll
        for (int ni = 0; ni < 4; ni++)
#pragma unroll
            for (int q = 0; q < 4; q++) c[mi][ni][q] = 0.0f;

#pragma unroll
    for (int kk = 0; kk < 8; kk++) {
        int kb = kk * 16;
        unsigned int a[2][4];
#pragma unroll
        for (int mi = 0; mi < 2; mi++) {
            const __half* base = As + (wm * 32 + mi * 16 + gr) * AS_STRIDE + kb + ck;
            a[mi][0] = *(const unsigned int*)(base);
            a[mi][1] = *(const unsigned int*)(base + 8 * AS_STRIDE);
            a[mi][2] = *(const unsigned int*)(base + 8);
            a[mi][3] = *(const unsigned int*)(base + 8 * AS_STRIDE + 8);
        }
#pragma unroll
        for (int ni = 0; ni < 4; ni++) {
            const __half* bb = Bs + (wn * 32 + ni * 8 + gr) * AS_STRIDE + kb + ck;
            unsigned int b0 = *(const unsigned int*)(bb);
            unsigned int b1 = *(const unsigned int*)(bb + 8);
#pragma unroll
            for (int mi = 0; mi < 2; mi++) {
                asm volatile(
                    "mma.sync.aligned.m16n8k16.row.col.f32.f16.f16.f32 "
                    "{%0,%1,%2,%3}, {%4,%5,%6,%7}, {%8,%9}, {%0,%1,%2,%3};"
                    : "+f"(c[mi][ni][0]), "+f"(c[mi][ni][1]),
                      "+f"(c[mi][ni][2]), "+f"(c[mi][ni][3])
                    : "r"(a[mi][0]), "r"(a[mi][1]), "r"(a[mi][2]), "r"(a[mi][3]),
                      "r"(b0), "r"(b1));
            }
        }
    }

    // ---- staged epilogue: C -> smem (As) -> coalesced uint4 stores ----
    __syncthreads();   // all fragment reads of As done
    const int cc = (lane & 3) * 2;
#pragma unroll
    for (int mi = 0; mi < 2; mi++) {
#pragma unroll
        for (int ni = 0; ni < 4; ni++) {
            int row = wm * 32 + mi * 16 + gr;         // 0..127 local
            int col = wn * 32 + ni * 8 + cc;          // 0..127 halves
            __half2 h0 = __floats2half2_rn(c[mi][ni][0], c[mi][ni][1]);
            __half2 h1 = __floats2half2_rn(c[mi][ni][2], c[mi][ni][3]);
            *(unsigned int*)(As + row * AS_STRIDE + col)       = *(unsigned int*)&h0;
            *(unsigned int*)(As + (row + 8) * AS_STRIDE + col) = *(unsigned int*)&h1;
        }
    }
    __syncthreads();
#pragma unroll
    for (int it = 0; it < 4; it++) {
        int i = tid + it * 512;          // uint4 slot, 0..2047
        int r = i >> 4, cq = i & 15;
        if (row0 + r < NN)
            *(uint4*)(g_Th + (size_t)(row0 + r) * FD + cq * 8) =
                *(const uint4*)(As + r * AS_STRIDE + cq * 8);
    }
}

// ---------------- fused aggregation: half-warp per node, unroll-8 (R9 version) ----------------
__device__ __forceinline__ void acc8(float* a, uint4 u, float w) {
    __half2 h; float2 f;
    h = *(__half2*)&u.x; f = __half22float2(h);
    a[0] = fmaf(f.x, w, a[0]); a[1] = fmaf(f.y, w, a[1]);
    h = *(__half2*)&u.y; f = __half22float2(h);
    a[2] = fmaf(f.x, w, a[2]); a[3] = fmaf(f.y, w, a[3]);
    h = *(__half2*)&u.z; f = __half22float2(h);
    a[4] = fmaf(f.x, w, a[4]); a[5] = fmaf(f.y, w, a[5]);
    h = *(__half2*)&u.w; f = __half22float2(h);
    a[6] = fmaf(f.x, w, a[6]); a[7] = fmaf(f.y, w, a[7]);
}

// mode 0: write relu(acc) half -> g_Xh; mode 1: write acc half (no relu) -> g_Xh
__global__ void __launch_bounds__(256) aggregate(int mode, const float* __restrict__ bias) {
    int gwarp = (blockIdx.x * 256 + threadIdx.x) >> 5;
    int lane = threadIdx.x & 31;
    int node = gwarp * 2 + (lane >> 4);
    int ln = lane & 15;
    if (node >= NN) return;
    int beg = g_rowptr[node], end = g_rowptr[node + 1];
    float di = g_dinv[node];
    float cnorm = di * di;

    float a[8];
    {
        float4 b0 = *(const float4*)(bias + ln * 8);
        float4 b1 = *(const float4*)(bias + ln * 8 + 4);
        a[0] = b0.x; a[1] = b0.y; a[2] = b0.z; a[3] = b0.w;
        a[4] = b1.x; a[5] = b1.y; a[6] = b1.z; a[7] = b1.w;
    }
    {
        uint4 u = *(const uint4*)(g_Th + (size_t)node * FD + ln * 8);
        acc8(a, u, cnorm);
    }

    int i = beg;
    for (; i + 8 <= end; i += 8) {
        float2 e0 = __ldcs(&g_sw[i + 0]);
        float2 e1 = __ldcs(&g_sw[i + 1]);
        float2 e2 = __ldcs(&g_sw[i + 2]);
        float2 e3 = __ldcs(&g_sw[i + 3]);
        float2 e4 = __ldcs(&g_sw[i + 4]);
        float2 e5 = __ldcs(&g_sw[i + 5]);
        float2 e6 = __ldcs(&g_sw[i + 6]);
        float2 e7 = __ldcs(&g_sw[i + 7]);
        uint4 u0 = *(const uint4*)(g_Th + (size_t)__float_as_int(e0.x) * FD + ln * 8);
        uint4 u1 = *(const uint4*)(g_Th + (size_t)__float_as_int(e1.x) * FD + ln * 8);
        uint4 u2 = *(const uint4*)(g_Th + (size_t)__float_as_int(e2.x) * FD + ln * 8);
        uint4 u3 = *(const uint4*)(g_Th + (size_t)__float_as_int(e3.x) * FD + ln * 8);
        uint4 u4 = *(const uint4*)(g_Th + (size_t)__float_as_int(e4.x) * FD + ln * 8);
        uint4 u5 = *(const uint4*)(g_Th + (size_t)__float_as_int(e5.x) * FD + ln * 8);
        uint4 u6 = *(const uint4*)(g_Th + (size_t)__float_as_int(e6.x) * FD + ln * 8);
        uint4 u7 = *(const uint4*)(g_Th + (size_t)__float_as_int(e7.x) * FD + ln * 8);
        acc8(a, u0, e0.y);
        acc8(a, u1, e1.y);
        acc8(a, u2, e2.y);
        acc8(a, u3, e3.y);
        acc8(a, u4, e4.y);
        acc8(a, u5, e5.y);
        acc8(a, u6, e6.y);
        acc8(a, u7, e7.y);
    }
    if (i + 4 <= end) {
        float2 e0 = __ldcs(&g_sw[i + 0]);
        float2 e1 = __ldcs(&g_sw[i + 1]);
        float2 e2 = __ldcs(&g_sw[i + 2]);
        float2 e3 = __ldcs(&g_sw[i + 3]);
        uint4 u0 = *(const uint4*)(g_Th + (size_t)__float_as_int(e0.x) * FD + ln * 8);
        uint4 u1 = *(const uint4*)(g_Th + (size_t)__float_as_int(e1.x) * FD + ln * 8);
        uint4 u2 = *(const uint4*)(g_Th + (size_t)__float_as_int(e2.x) * FD + ln * 8);
        uint4 u3 = *(const uint4*)(g_Th + (size_t)__float_as_int(e3.x) * FD + ln * 8);
        acc8(a, u0, e0.y);
        acc8(a, u1, e1.y);
        acc8(a, u2, e2.y);
        acc8(a, u3, e3.y);
        i += 4;
    }
    for (; i < end; i++) {
        float2 e0 = __ldcs(&g_sw[i]);
        uint4 u0 = *(const uint4*)(g_Th + (size_t)__float_as_int(e0.x) * FD + ln * 8);
        acc8(a, u0, e0.y);
    }

    if (mode == 0) {
#pragma unroll
        for (int q = 0; q < 8; q++) a[q] = fmaxf(a[q], 0.f);
    }
    __half2 h0 = __floats2half2_rn(a[0], a[1]);
    __half2 h1 = __floats2half2_rn(a[2], a[3]);
    __half2 h2 = __floats2half2_rn(a[4], a[5]);
    __half2 h3 = __floats2half2_rn(a[6], a[7]);
    uint4 u;
    u.x = *(unsigned int*)&h0;
    u.y = *(unsigned int*)&h1;
    u.z = *(unsigned int*)&h2;
    u.w = *(unsigned int*)&h3;
    *(uint4*)(g_Xh + (size_t)node * FD + ln * 8) = u;
}

// ---------------- pooling: 64 nodes per block ----------------
#define POOL_NODES 64
__global__ void __launch_bounds__(128) pool_accum(const void* __restrict__ batch, int n) {
    __shared__ int sb[POOL_NODES];
    int f  = threadIdx.x;
    int v0 = blockIdx.x * POOL_NODES;
    for (int i = f; i < POOL_NODES; i += 128) {
        int v = v0 + i;
        sb[i] = (v < n) ? batch_at(batch, v) : -1;
    }
    __syncthreads();
    float acc = 0.f, ccnt = 0.f;
    int curg = -1;
    for (int i = 0; i < POOL_NODES; i++) {
        int g = sb[i];
        if (g < 0) break;
        if (g != curg) {
            if (curg >= 0) {
                atomicAdd(&g_sums[curg * FD + f], acc);
                if (f == 0) atomicAdd(&g_cnt[curg], ccnt);
            }
            acc = 0.f; ccnt = 0.f; curg = g;
        }
        acc  += __half2float(g_Xh[(size_t)(v0 + i) * FD + f]);
        ccnt += 1.f;
    }
    if (curg >= 0) {
        atomicAdd(&g_sums[curg * FD + f], acc);
        if (f == 0) atomicAdd(&g_cnt[curg], ccnt);
    }
}

// ---------------- finalize ----------------
__global__ void __launch_bounds__(128) finalize(
    const float* __restrict__ Wlin, const float* __restrict__ blin,
    float* __restrict__ out, int out_size)
{
    int g = blockIdx.x;
    int f = threadIdx.x;
    __shared__ float se[FD];
    float e = g_sums[g * FD + f] / fmaxf(g_cnt[g], 1.0f);
    se[f] = e;
    if (out_size >= NG * NC + NG * FD)
        out[NG * NC + g * FD + f] = e;
    __syncthreads();
    if (f < NC) {
        float s = blin[f];
#pragma unroll
        for (int k = 0; k < FD; k++)
            s = fmaf(se[k], Wlin[k * NC + f], s);
        out[g * NC + f] = s;
    }
}

// ---------------- launch ----------------
extern "C" void kernel_launch(void* const* d_in, const int* in_sizes, int n_in,
                              void* d_out, int out_size) {
    const float* x    = (const float*)d_in[0];
    const void*  ei   = d_in[1];
    const void*  batch= d_in[2];
    const float* W1   = (const float*)d_in[3];
    const float* b1   = (const float*)d_in[4];
    const float* W2   = (const float*)d_in[5];
    const float* b2   = (const float*)d_in[6];
    const float* W3   = (const float*)d_in[7];
    const float* b3   = (const float*)d_in[8];
    const float* Wlin = (const float*)d_in[9];
    const float* blin = (const float*)d_in[10];
    float* out = (float*)d_out;
    const int n = NN;

    const int gemm_grid = (NN + 127) / 128;
    const int agg_grid  = (NN * 16 + 255) / 256;

    init_all   <<<(NN + 255) / 256, 256>>>((const int*)batch, W1, W2, W3); // 0
    count_edges<<<(NE + 255) / 256, 256>>>(ei);                            // 1
    gemm_h     <<<gemm_grid, 512>>>(x, 0);                                 // 2
    scan1      <<<SCAN_BLOCKS, 256>>>();                                   // 3
    scan2      <<<1, 128>>>();                                             // 4
    scan3      <<<SCAN_BLOCKS, 256>>>();                                   // 5
    fill_csr   <<<(NE + 255) / 256, 256>>>(ei);                            // 6

    aggregate  <<<agg_grid, 256>>>(0, b1);     // -> relu half Xh
    gemm_h     <<<gemm_grid, 512>>>(nullptr, 1);
    aggregate  <<<agg_grid, 256>>>(0, b2);     // -> relu half Xh
    gemm_h     <<<gemm_grid, 512>>>(nullptr, 2);
    aggregate  <<<agg_grid, 256>>>(1, b3);     // -> half Xh (no relu)

    pool_accum<<<(NN + POOL_NODES - 1) / POOL_NODES, 128>>>(batch, n);
    finalize  <<<NG, 128>>>(Wlin, blin, out, out_size);
}

// round 13
// speedup vs baseline: 1.1376x; 1.0076x over previous
#include <cuda_runtime.h>
#include <cuda_fp16.h>
#include <cstdint>

#define NN 100000
#define FD 128
#define NE 1600000
#define NG 64
#define NC 10
#define SCAN_CHUNK 1024
#define SCAN_BLOCKS ((NN + SCAN_CHUNK - 1) / SCAN_CHUNK)   // 98
#define GEMM_GRID ((NN + 127) / 128)                        // 782
#define COUNT_GRID ((NE + 2047) / 2048)                     // 782

// ---------------- scratch ----------------
__device__ __half  g_Xh[(size_t)NN * FD];  // activations (half)
__device__ __half  g_Th[(size_t)NN * FD];  // GEMM output (half, gather source)
__device__ __half  g_Wt[3 * FD * FD];      // all W, transposed, half
__device__ float   g_dinv[NN];
__device__ int     g_cntN[NN];
__device__ int     g_rowptr[NN + 1];
__device__ int     g_pos[NN];
__device__ int     g_bsum[128];
__device__ float2  g_sw[NE];               // .x = src (bits), .y = edge weight
__device__ float   g_sums[NG * FD];
__device__ float   g_cnt [NG];
__device__ int     g_is64;

__device__ __forceinline__ int edge_src(const void* ei, int e) {
    return g_is64 ? (int)((const long long*)ei)[e] : ((const int*)ei)[e];
}
__device__ __forceinline__ int edge_dst(const void* ei, int e) {
    return g_is64 ? (int)((const long long*)ei)[(size_t)NE + e]
                  : ((const int*)ei)[(size_t)NE + e];
}
__device__ __forceinline__ int batch_at(const void* b, int v) {
    return g_is64 ? (int)((const long long*)b)[v] : ((const int*)b)[v];
}

// ---------------- fused init: zero counts/pool + convert W + detect dtype ----------------
__global__ void init_all(const int* __restrict__ batch_words,
                         const float* __restrict__ W1,
                         const float* __restrict__ W2,
                         const float* __restrict__ W3) {
    int i = blockIdx.x * blockDim.x + threadIdx.x;
    if (i < NN) g_cntN[i] = 0;
    if (i < NG * FD) g_sums[i] = 0.0f;
    if (i < NG) g_cnt[i] = 0.0f;
    if (i < 3 * FD * FD) {
        int l = i / (FD * FD);
        int j = i % (FD * FD);
        const float* W = (l == 0) ? W1 : (l == 1) ? W2 : W3;
        int k = j >> 7, n = j & 127;
        g_Wt[l * FD * FD + n * FD + k] = __float2half_rn(W[j]);
    }
    if (blockIdx.x == 0) {
        __shared__ int found;
        if (threadIdx.x == 0) found = 0;
        __syncthreads();
        int local = 0;
        for (int t = threadIdx.x; t < NN / 2; t += blockDim.x)
            if (batch_words[2 * t + 1] != 0) local = 1;
        if (local) atomicOr(&found, 1);
        __syncthreads();
        if (threadIdx.x == 0) g_is64 = (found == 0) ? 1 : 0;
    }
}

// ---------------- GEMM body (shared by gemm_h and gemm1_count) ----------------
#define AS_STRIDE 136
__device__ __forceinline__ void gemm_body(const float* __restrict__ Xf, int wsel,
                                          int row0, __half* As, __half* Bs) {
    const int tid  = threadIdx.x;
    const int warp = tid >> 5;
    const int lane = tid & 31;
    const int wm = warp >> 2;       // 0..3
    const int wn = warp & 3;        // 0..3
    const int gr = lane >> 2;       // 0..7
    const int ck = (lane & 3) * 2;  // 0,2,4,6
    const __half* Wt = g_Wt + wsel * FD * FD;

    if (Xf != nullptr) {
#pragma unroll
        for (int it = 0; it < 8; it++) {
            int i = tid + it * 512;          // float4 slot, 0..4095
            int r = i >> 5, c4 = i & 31;
            float4 v = make_float4(0.f, 0.f, 0.f, 0.f);
            if (row0 + r < NN)
                v = *(const float4*)(Xf + (size_t)(row0 + r) * FD + c4 * 4);
            __half2 h0 = __floats2half2_rn(v.x, v.y);
            __half2 h1 = __floats2half2_rn(v.z, v.w);
            uint2 u;
            u.x = *(unsigned int*)&h0;
            u.y = *(unsigned int*)&h1;
            *(uint2*)(As + r * AS_STRIDE + c4 * 4) = u;
        }
    } else {
#pragma unroll
        for (int it = 0; it < 4; it++) {
            int i = tid + it * 512;          // uint4 slot, 0..2047
            int r = i >> 4, kq = i & 15;
            uint4 v = make_uint4(0u, 0u, 0u, 0u);
            if (row0 + r < NN)
                v = *(const uint4*)(g_Xh + (size_t)(row0 + r) * FD + kq * 8);
            *(uint4*)(As + r * AS_STRIDE + kq * 8) = v;
        }
    }
#pragma unroll
    for (int it = 0; it < 4; it++) {
        int i = tid + it * 512;
        int nr = i >> 4, kq = i & 15;
        *(uint4*)(Bs + nr * AS_STRIDE + kq * 8) =
            *(const uint4*)(Wt + nr * FD + kq * 8);
    }
    __syncthreads();

    float c[2][4][4];
#pragma unroll
    for (int mi = 0; mi < 2; mi++)
#pragma unroll
        for (int ni = 0; ni < 4; ni++)
#pragma unroll
            for (int q = 0; q < 4; q++) c[mi][ni][q] = 0.0f;

#pragma unroll
    for (int kk = 0; kk < 8; kk++) {
        int kb = kk * 16;
        unsigned int a[2][4];
#pragma unroll
        for (int mi = 0; mi < 2; mi++) {
            const __half* base = As + (wm * 32 + mi * 16 + gr) * AS_STRIDE + kb + ck;
            a[mi][0] = *(const unsigned int*)(base);
            a[mi][1] = *(const unsigned int*)(base + 8 * AS_STRIDE);
            a[mi][2] = *(const unsigned int*)(base + 8);
            a[mi][3] = *(const unsigned int*)(base + 8 * AS_STRIDE + 8);
        }
#pragma unroll
        for (int ni = 0; ni < 4; ni++) {
            const __half* bb = Bs + (wn * 32 + ni * 8 + gr) * AS_STRIDE + kb + ck;
            unsigned int b0 = *(const unsigned int*)(bb);
            unsigned int b1 = *(const unsigned int*)(bb + 8);
#pragma unroll
            for (int mi = 0; mi < 2; mi++) {
                asm volatile(
                    "mma.sync.aligned.m16n8k16.row.col.f32.f16.f16.f32 "
                    "{%0,%1,%2,%3}, {%4,%5,%6,%7}, {%8,%9}, {%0,%1,%2,%3};"
                    : "+f"(c[mi][ni][0]), "+f"(c[mi][ni][1]),
                      "+f"(c[mi][ni][2]), "+f"(c[mi][ni][3])
                    : "r"(a[mi][0]), "r"(a[mi][1]), "r"(a[mi][2]), "r"(a[mi][3]),
                      "r"(b0), "r"(b1));
            }
        }
    }

    // staged epilogue: C -> smem (As) -> coalesced uint4 stores
    __syncthreads();
    const int cc = (lane & 3) * 2;
#pragma unroll
    for (int mi = 0; mi < 2; mi++) {
#pragma unroll
        for (int ni = 0; ni < 4; ni++) {
            int row = wm * 32 + mi * 16 + gr;
            int col = wn * 32 + ni * 8 + cc;
            __half2 h0 = __floats2half2_rn(c[mi][ni][0], c[mi][ni][1]);
            __half2 h1 = __floats2half2_rn(c[mi][ni][2], c[mi][ni][3]);
            *(unsigned int*)(As + row * AS_STRIDE + col)       = *(unsigned int*)&h0;
            *(unsigned int*)(As + (row + 8) * AS_STRIDE + col) = *(unsigned int*)&h1;
        }
    }
    __syncthreads();
#pragma unroll
    for (int it = 0; it < 4; it++) {
        int i = tid + it * 512;
        int r = i >> 4, cq = i & 15;
        if (row0 + r < NN)
            *(uint4*)(g_Th + (size_t)(row0 + r) * FD + cq * 8) =
                *(const uint4*)(As + r * AS_STRIDE + cq * 8);
    }
}

// ---------------- fused: gemm layer-1 + edge counting (independent work) ----------------
__global__ void __launch_bounds__(512) gemm1_count(const float* __restrict__ Xf,
                                                   const void* __restrict__ ei) {
    __shared__ __align__(16) __half As[128 * AS_STRIDE];
    __shared__ __align__(16) __half Bs[128 * AS_STRIDE];
    if (blockIdx.x < GEMM_GRID) {
        gemm_body(Xf, 0, blockIdx.x * 128, As, Bs);
    } else {
        int b = blockIdx.x - GEMM_GRID;
        int e = b * 2048 + threadIdx.x;
#pragma unroll
        for (int it = 0; it < 4; it++, e += 512) {
            if (e < NE) atomicAdd(&g_cntN[edge_dst(ei, e)], 1);
        }
    }
}

// ---------------- plain GEMM kernel (layers 2/3) ----------------
__global__ void __launch_bounds__(512) gemm_h(const float* __restrict__ Xf, int wsel) {
    __shared__ __align__(16) __half As[128 * AS_STRIDE];
    __shared__ __align__(16) __half Bs[128 * AS_STRIDE];
    gemm_body(Xf, wsel, blockIdx.x * 128, As, Bs);
}

// ---------------- scan (3 phases); scan1 also computes dinv ----------------
__global__ void __launch_bounds__(256) scan1() {
    __shared__ int warp_tot[8];
    int base = blockIdx.x * SCAN_CHUNK + threadIdx.x * 4;
    int lane = threadIdx.x & 31, w = threadIdx.x >> 5;
    int v0 = (base + 0 < NN) ? g_cntN[base + 0] : 0;
    int v1 = (base + 1 < NN) ? g_cntN[base + 1] : 0;
    int v2 = (base + 2 < NN) ? g_cntN[base + 2] : 0;
    int v3 = (base + 3 < NN) ? g_cntN[base + 3] : 0;
    if (base + 0 < NN) g_dinv[base + 0] = rsqrtf((float)(v0 + 1));
    if (base + 1 < NN) g_dinv[base + 1] = rsqrtf((float)(v1 + 1));
    if (base + 2 < NN) g_dinv[base + 2] = rsqrtf((float)(v2 + 1));
    if (base + 3 < NN) g_dinv[base + 3] = rsqrtf((float)(v3 + 1));
    int tot = v0 + v1 + v2 + v3;
    int inc = tot;
#pragma unroll
    for (int o = 1; o < 32; o <<= 1) {
        int t = __shfl_up_sync(~0u, inc, o);
        if (lane >= o) inc += t;
    }
    if (lane == 31) warp_tot[w] = inc;
    __syncthreads();
    if (w == 0 && lane < 8) {
        int t = warp_tot[lane];
#pragma unroll
        for (int o = 1; o < 8; o <<= 1) {
            int u = __shfl_up_sync(0xffu, t, o);
            if (lane >= o) t += u;
        }
        warp_tot[lane] = t;
    }
    __syncthreads();
    int excl = ((w > 0) ? warp_tot[w - 1] : 0) + (inc - tot);
    if (base + 0 < NN) g_rowptr[base + 0] = excl;
    if (base + 1 < NN) g_rowptr[base + 1] = excl + v0;
    if (base + 2 < NN) g_rowptr[base + 2] = excl + v0 + v1;
    if (base + 3 < NN) g_rowptr[base + 3] = excl + v0 + v1 + v2;
    if (threadIdx.x == 255) g_bsum[blockIdx.x] = warp_tot[7];
}
__global__ void __launch_bounds__(128) scan2() {
    __shared__ int wt[4];
    int tid = threadIdx.x, lane = tid & 31, w = tid >> 5;
    int v = (tid < SCAN_BLOCKS) ? g_bsum[tid] : 0;
    int inc = v;
#pragma unroll
    for (int o = 1; o < 32; o <<= 1) {
        int t = __shfl_up_sync(~0u, inc, o);
        if (lane >= o) inc += t;
    }
    if (lane == 31) wt[w] = inc;
    __syncthreads();
    if (w == 0 && lane < 4) {
        int t = wt[lane];
#pragma unroll
        for (int o = 1; o < 4; o <<= 1) {
            int u = __shfl_up_sync(0xfu, t, o);
            if (lane >= o) t += u;
        }
        wt[lane] = t;
    }
    __syncthreads();
    int excl = ((w > 0) ? wt[w - 1] : 0) + (inc - v);
    if (tid < SCAN_BLOCKS) g_bsum[tid] = excl;
    if (tid == 0) g_rowptr[NN] = NE;
}
__global__ void __launch_bounds__(256) scan3() {
    int off = g_bsum[blockIdx.x];
    int base = blockIdx.x * SCAN_CHUNK + threadIdx.x * 4;
#pragma unroll
    for (int j = 0; j < 4; j++) {
        int idx = base + j;
        if (idx < NN) {
            int val = g_rowptr[idx] + off;
            g_rowptr[idx] = val;
            g_pos[idx] = val;
        }
    }
}
__global__ void fill_csr(const void* __restrict__ ei) {
    int e = blockIdx.x * blockDim.x + threadIdx.x;
    if (e >= NE) return;
    int s = edge_src(ei, e);
    int d = edge_dst(ei, e);
    int p = atomicAdd(&g_pos[d], 1);
    g_sw[p] = make_float2(__int_as_float(s), g_dinv[s] * g_dinv[d]);
}

// ---------------- fused aggregation: half-warp per node, unroll-8 (R9 version) ----------------
__device__ __forceinline__ void acc8(float* a, uint4 u, float w) {
    __half2 h; float2 f;
    h = *(__half2*)&u.x; f = __half22float2(h);
    a[0] = fmaf(f.x, w, a[0]); a[1] = fmaf(f.y, w, a[1]);
    h = *(__half2*)&u.y; f = __half22float2(h);
    a[2] = fmaf(f.x, w, a[2]); a[3] = fmaf(f.y, w, a[3]);
    h = *(__half2*)&u.z; f = __half22float2(h);
    a[4] = fmaf(f.x, w, a[4]); a[5] = fmaf(f.y, w, a[5]);
    h = *(__half2*)&u.w; f = __half22float2(h);
    a[6] = fmaf(f.x, w, a[6]); a[7] = fmaf(f.y, w, a[7]);
}

// mode 0: write relu(acc) half -> g_Xh; mode 1: write acc half (no relu) -> g_Xh
__global__ void __launch_bounds__(256) aggregate(int mode, const float* __restrict__ bias) {
    int gwarp = (blockIdx.x * 256 + threadIdx.x) >> 5;
    int lane = threadIdx.x & 31;
    int node = gwarp * 2 + (lane >> 4);
    int ln = lane & 15;
    if (node >= NN) return;
    int beg = g_rowptr[node], end = g_rowptr[node + 1];
    float di = g_dinv[node];
    float cnorm = di * di;

    float a[8];
    {
        float4 b0 = *(const float4*)(bias + ln * 8);
        float4 b1 = *(const float4*)(bias + ln * 8 + 4);
        a[0] = b0.x; a[1] = b0.y; a[2] = b0.z; a[3] = b0.w;
        a[4] = b1.x; a[5] = b1.y; a[6] = b1.z; a[7] = b1.w;
    }
    {
        uint4 u = *(const uint4*)(g_Th + (size_t)node * FD + ln * 8);
        acc8(a, u, cnorm);
    }

    int i = beg;
    for (; i + 8 <= end; i += 8) {
        float2 e0 = __ldcs(&g_sw[i + 0]);
        float2 e1 = __ldcs(&g_sw[i + 1]);
        float2 e2 = __ldcs(&g_sw[i + 2]);
        float2 e3 = __ldcs(&g_sw[i + 3]);
        float2 e4 = __ldcs(&g_sw[i + 4]);
        float2 e5 = __ldcs(&g_sw[i + 5]);
        float2 e6 = __ldcs(&g_sw[i + 6]);
        float2 e7 = __ldcs(&g_sw[i + 7]);
        uint4 u0 = *(const uint4*)(g_Th + (size_t)__float_as_int(e0.x) * FD + ln * 8);
        uint4 u1 = *(const uint4*)(g_Th + (size_t)__float_as_int(e1.x) * FD + ln * 8);
        uint4 u2 = *(const uint4*)(g_Th + (size_t)__float_as_int(e2.x) * FD + ln * 8);
        uint4 u3 = *(const uint4*)(g_Th + (size_t)__float_as_int(e3.x) * FD + ln * 8);
        uint4 u4 = *(const uint4*)(g_Th + (size_t)__float_as_int(e4.x) * FD + ln * 8);
        uint4 u5 = *(const uint4*)(g_Th + (size_t)__float_as_int(e5.x) * FD + ln * 8);
        uint4 u6 = *(const uint4*)(g_Th + (size_t)__float_as_int(e6.x) * FD + ln * 8);
        uint4 u7 = *(const uint4*)(g_Th + (size_t)__float_as_int(e7.x) * FD + ln * 8);
        acc8(a, u0, e0.y);
        acc8(a, u1, e1.y);
        acc8(a, u2, e2.y);
        acc8(a, u3, e3.y);
        acc8(a, u4, e4.y);
        acc8(a, u5, e5.y);
        acc8(a, u6, e6.y);
        acc8(a, u7, e7.y);
    }
    if (i + 4 <= end) {
        float2 e0 = __ldcs(&g_sw[i + 0]);
        float2 e1 = __ldcs(&g_sw[i + 1]);
        float2 e2 = __ldcs(&g_sw[i + 2]);
        float2 e3 = __ldcs(&g_sw[i + 3]);
        uint4 u0 = *(const uint4*)(g_Th + (size_t)__float_as_int(e0.x) * FD + ln * 8);
        uint4 u1 = *(const uint4*)(g_Th + (size_t)__float_as_int(e1.x) * FD + ln * 8);
        uint4 u2 = *(const uint4*)(g_Th + (size_t)__float_as_int(e2.x) * FD + ln * 8);
        uint4 u3 = *(const uint4*)(g_Th + (size_t)__float_as_int(e3.x) * FD + ln * 8);
        acc8(a, u0, e0.y);
        acc8(a, u1, e1.y);
        acc8(a, u2, e2.y);
        acc8(a, u3, e3.y);
        i += 4;
    }
    for (; i < end; i++) {
        float2 e0 = __ldcs(&g_sw[i]);
        uint4 u0 = *(const uint4*)(g_Th + (size_t)__float_as_int(e0.x) * FD + ln * 8);
        acc8(a, u0, e0.y);
    }

    if (mode == 0) {
#pragma unroll
        for (int q = 0; q < 8; q++) a[q] = fmaxf(a[q], 0.f);
    }
    __half2 h0 = __floats2half2_rn(a[0], a[1]);
    __half2 h1 = __floats2half2_rn(a[2], a[3]);
    __half2 h2 = __floats2half2_rn(a[4], a[5]);
    __half2 h3 = __floats2half2_rn(a[6], a[7]);
    uint4 u;
    u.x = *(unsigned int*)&h0;
    u.y = *(unsigned int*)&h1;
    u.z = *(unsigned int*)&h2;
    u.w = *(unsigned int*)&h3;
    *(uint4*)(g_Xh + (size_t)node * FD + ln * 8) = u;
}

// ---------------- pooling: 64 nodes per block ----------------
#define POOL_NODES 64
__global__ void __launch_bounds__(128) pool_accum(const void* __restrict__ batch, int n) {
    __shared__ int sb[POOL_NODES];
    int f  = threadIdx.x;
    int v0 = blockIdx.x * POOL_NODES;
    for (int i = f; i < POOL_NODES; i += 128) {
        int v = v0 + i;
        sb[i] = (v < n) ? batch_at(batch, v) : -1;
    }
    __syncthreads();
    float acc = 0.f, ccnt = 0.f;
    int curg = -1;
    for (int i = 0; i < POOL_NODES; i++) {
        int g = sb[i];
        if (g < 0) break;
        if (g != curg) {
            if (curg >= 0) {
                atomicAdd(&g_sums[curg * FD + f], acc);
                if (f == 0) atomicAdd(&g_cnt[curg], ccnt);
            }
            acc = 0.f; ccnt = 0.f; curg = g;
        }
        acc  += __half2float(g_Xh[(size_t)(v0 + i) * FD + f]);
        ccnt += 1.f;
    }
    if (curg >= 0) {
        atomicAdd(&g_sums[curg * FD + f], acc);
        if (f == 0) atomicAdd(&g_cnt[curg], ccnt);
    }
}

// ---------------- finalize ----------------
__global__ void __launch_bounds__(128) finalize(
    const float* __restrict__ Wlin, const float* __restrict__ blin,
    float* __restrict__ out, int out_size)
{
    int g = blockIdx.x;
    int f = threadIdx.x;
    __shared__ float se[FD];
    float e = g_sums[g * FD + f] / fmaxf(g_cnt[g], 1.0f);
    se[f] = e;
    if (out_size >= NG * NC + NG * FD)
        out[NG * NC + g * FD + f] = e;
    __syncthreads();
    if (f < NC) {
        float s = blin[f];
#pragma unroll
        for (int k = 0; k < FD; k++)
            s = fmaf(se[k], Wlin[k * NC + f], s);
        out[g * NC + f] = s;
    }
}

// ---------------- launch ----------------
extern "C" void kernel_launch(void* const* d_in, const int* in_sizes, int n_in,
                              void* d_out, int out_size) {
    const float* x    = (const float*)d_in[0];
    const void*  ei   = d_in[1];
    const void*  batch= d_in[2];
    const float* W1   = (const float*)d_in[3];
    const float* b1   = (const float*)d_in[4];
    const float* W2   = (const float*)d_in[5];
    const float* b2   = (const float*)d_in[6];
    const float* W3   = (const float*)d_in[7];
    const float* b3   = (const float*)d_in[8];
    const float* Wlin = (const float*)d_in[9];
    const float* blin = (const float*)d_in[10];
    float* out = (float*)d_out;
    const int n = NN;

    const int agg_grid = (NN * 16 + 255) / 256;

    init_all   <<<(NN + 255) / 256, 256>>>((const int*)batch, W1, W2, W3); // 0
    gemm1_count<<<GEMM_GRID + COUNT_GRID, 512>>>(x, ei);                   // 1 (gemm L1 + count fused)
    scan1      <<<SCAN_BLOCKS, 256>>>();                                   // 2
    scan2      <<<1, 128>>>();                                             // 3
    scan3      <<<SCAN_BLOCKS, 256>>>();                                   // 4
    fill_csr   <<<(NE + 255) / 256, 256>>>(ei);                            // 5

    aggregate  <<<agg_grid, 256>>>(0, b1);     // -> relu half Xh
    gemm_h     <<<GEMM_GRID, 512>>>(nullptr, 1);
    aggregate  <<<agg_grid, 256>>>(0, b2);     // -> relu half Xh
    gemm_h     <<<GEMM_GRID, 512>>>(nullptr, 2);
    aggregate  <<<agg_grid, 256>>>(1, b3);     // -> half Xh (no relu)

    pool_accum<<<(NN + POOL_NODES - 1) / POOL_NODES, 128>>>(batch, n);
    finalize  <<<NG, 128>>>(Wlin, blin, out, out_size);
}